// round 2
// baseline (speedup 1.0000x reference)
#include <cuda_runtime.h>
#include <cstdint>

// HIRNN (GR4J-style) forward: B independent chains, T serial steps.
// Q[t] (t>=1) uses the pre-step state at t  -> computed inside the scan loop.
// Q[0] uses the FINAL state (roll shift=1)  -> recomputed after the loop.
//
// heaviside(1e7*x) select pairs are rewritten as exact min/max (arms agree at
// ties); clip(+-1e5) proven inactive (|SMF-ETS| <= 410, |RECnew-BAS| <= 800).

__device__ __forceinline__ float ex2f(float x) {
    float y;
    asm("ex2.approx.f32 %0, %1;" : "=f"(y) : "f"(x));
    return y;
}

struct Params {
    float INSC, COEFF, SMSC, SUB, CRAK, RecK, invSMSC, ck;
};

// One timestep: advances (SMS, GW), returns Q computed from the PRE-step state.
__device__ __forceinline__ float stepq(float Prec, float PET,
                                       float& SMS, float& GW, const Params& p)
{
    // interception (state-independent)
    float IMAX = fmaxf(fminf(p.INSC, PET), 0.f);
    float INT  = fmaxf(fminf(IMAX, Prec), 0.f);
    float INR  = fmaxf(Prec - INT, 0.f);
    float POT  = fmaxf(PET - INT, 0.f);

    // soil fluxes (SMS is already clamped to [0, SMSC])
    float e     = ex2f(p.ck * SMS);          // exp(-SQ*SMS/SMSC)
    float cap   = p.COEFF * e;
    float RMO   = fminf(cap, INR);           // heaviside-pair == min; both >= 0
    float ratio = SMS * p.invSMSC;           // in [0,1]
    float SRUN  = (p.SUB * ratio) * RMO;     // >= 0, <= RMO
    float RS    = RMO - SRUN;                // >= 0
    float REC   = (p.CRAK * ratio) * RS;     // >= 0, <= RS
    float SMF   = RS - REC;                  // >= 0
    float ETS   = fminf(10.f * ratio, POT);  // heaviside-pair == min; >= 0

    // Q from pre-step state
    float BAS  = fmaxf(p.RecK * GW, 0.f);    // heaviside(GW)*RecK*GW
    float IRUN = fmaxf(INR - RMO, 0.f);
    float DR   = fmaxf(SRUN + IRUN, 0.f);
    float q    = fmaxf(DR + BAS, 0.f);

    // state advance (clip +-1e5 provably inactive)
    float d    = SMF - ETS;                  // in [-10, 400]
    float s    = SMS + d;                    // pre-clamp value used by recharge
    float RECn = REC + fmaxf(s - p.SMSC, 0.f);
    GW  = GW + (RECn - BAS);
    SMS = fminf(fmaxf(s, 0.f), p.SMSC);      // next step's soil_moisture_store
    return q;
}

template <int T>
__global__ __launch_bounds__(32)
void hirnn_kernel(const float* __restrict__ in,
                  const float* __restrict__ pINSC,
                  const float* __restrict__ pCOEFF,
                  const float* __restrict__ pSQ,
                  const float* __restrict__ pSMSC,
                  const float* __restrict__ pSUB,
                  const float* __restrict__ pCRAK,
                  const float* __restrict__ pRecK,
                  float* __restrict__ out, int B)
{
    int b = blockIdx.x * 32 + threadIdx.x;
    if (b >= B) return;

    Params p;
    p.INSC  = fminf(fmaxf(pINSC[0]  * 5.f,   0.5f),   5.f);
    p.COEFF = fminf(fmaxf(pCOEFF[0] * 400.f, 50.f),   400.f);
    float SQ = fminf(fmaxf(pSQ[0]   * 6.f,   0.f),    6.f);
    p.SMSC  = fminf(fmaxf(pSMSC[0]  * 500.f, 50.f),   500.f);
    p.SUB   = fminf(fmaxf(pSUB[0],           0.f),    1.f);
    p.CRAK  = fminf(fmaxf(pCRAK[0],          0.f),    1.f);
    p.RecK  = fminf(fmaxf(pRecK[0]  * 0.3f,  0.003f), 0.3f);
    p.invSMSC = 1.f / p.SMSC;
    p.ck = -(SQ * p.invSMSC) * 1.44269504088896340736f;  // * log2(e)

    const float4* row  = reinterpret_cast<const float4*>(in + (size_t)b * T * 2);
    float4*       orow = reinterpret_cast<float4*>(out + (size_t)b * T);

    float SMS = 0.f, GW = 0.f;
    float Prec0 = 0.f, PET0 = 0.f;

    #pragma unroll 4
    for (int i = 0; i < T / 4; ++i) {
        float4 v0 = __ldg(&row[2 * i]);
        float4 v1 = __ldg(&row[2 * i + 1]);
        if (i == 0) { Prec0 = v0.x; PET0 = v0.y; }
        float4 q;
        q.x = stepq(v0.x, v0.y, SMS, GW, p);
        q.y = stepq(v0.z, v0.w, SMS, GW, p);
        q.z = stepq(v1.x, v1.y, SMS, GW, p);
        q.w = stepq(v1.z, v1.w, SMS, GW, p);
        orow[i] = q;  // q.x at i==0 is a placeholder, overwritten below
    }

    // Q[0]: roll(shift=1) puts the FINAL state at t=0.
    float S2 = SMS, G2 = GW;
    float q0 = stepq(Prec0, PET0, S2, G2, p);
    out[(size_t)b * T] = q0;
}

extern "C" void kernel_launch(void* const* d_in, const int* in_sizes, int n_in,
                              void* d_out, int out_size)
{
    const float* in    = (const float*)d_in[0];
    const float* INSC  = (const float*)d_in[1];
    const float* COEFF = (const float*)d_in[2];
    const float* SQ    = (const float*)d_in[3];
    const float* SMSC  = (const float*)d_in[4];
    const float* SUB   = (const float*)d_in[5];
    const float* CRAK  = (const float*)d_in[6];
    const float* RecK  = (const float*)d_in[7];
    float* out = (float*)d_out;

    constexpr int T = 1024;
    int B = out_size / T;                 // 4096 for this problem
    int blocks = (B + 31) / 32;
    hirnn_kernel<T><<<blocks, 32>>>(in, INSC, COEFF, SQ, SMSC, SUB, CRAK, RecK,
                                    out, B);
}

// round 3
// speedup vs baseline: 1.3431x; 1.3431x over previous
#include <cuda_runtime.h>
#include <cstdint>

// HIRNN (GR4J-style) forward, chain-minimized form.
// State kept normalized: u = clamp(SMS,0,SMSC)/SMSC in [0,1], so the per-step
// clamp is a single FFMA.SAT. Flux cascade factored as SMF = RMO * f(u) with
// f(u) computable in parallel with the MUFU.EX2 on the critical path.
// Loop-carried chain: FFMA -> MUFU.EX2 -> FMNMX -> FFMA.SAT (~29 cyc).
//
// Q[t] (t>=1) uses the pre-step state at t  -> computed inside the loop.
// Q[0] uses the FINAL state (roll shift=1)  -> recomputed after the loop.
// heaviside-select pairs == exact min/max; clip(+-1e5) provably inactive.

__device__ __forceinline__ float ex2f(float x) {
    float y;
    asm("ex2.approx.f32 %0, %1;" : "=f"(y) : "f"(x));
    return y;
}
__device__ __forceinline__ float fma_sat(float a, float b, float c) {
    float d;
    asm("fma.rn.sat.f32 %0, %1, %2, %3;" : "=f"(d) : "f"(a), "f"(b), "f"(c));
    return d;
}

struct Params {
    float INSC, SMSC, SUB, CRAK, RecK, invSMSC, ck2, lC;
};

// One step: advances (u, GW); returns Q computed from the PRE-step state.
__device__ __forceinline__ float stepq(float Prec, float PET,
                                       float& u, float& GW, const Params& p)
{
    // interception: INT = min(INSC, PET, Prec); all inputs >= 0, maxes exact-redundant
    float INT = fminf(fminf(p.INSC, PET), Prec);
    float INR = Prec - INT;            // >= 0 exactly
    float POT = PET - INT;             // >= 0 exactly

    // ---- critical chain ----
    float arg = fmaf(p.ck2, u, p.lC);  // log2(COEFF) - SQ*log2e*u
    float cap = ex2f(arg);             // COEFF * exp(-SQ*SMS/SMSC)
    float RMO = fminf(cap, INR);

    // ---- parallel state-polynomials (ready before RMO) ----
    float su   = p.SUB * u;
    float a    = fmaf(-p.SUB,  u, 1.f);   // 1 - SUB*u
    float b    = fmaf(-p.CRAK, u, 1.f);   // 1 - CRAK*u
    float cr   = p.CRAK * u;
    float f    = a * b;                   // SMF = RMO * f
    float fi   = f * p.invSMSC;
    float g    = cr * a;                  // REC = RMO * g
    float ETS  = fminf(10.f * u, POT);
    float base = fmaf(-ETS, p.invSMSC, u);

    // ---- chain tail: one FFMA.SAT = add + clamp to [0,1] ----
    float u_new = fma_sat(RMO, fi, base);
    float s_raw = fmaf(RMO, fi, base);    // pre-clamp, for recharge overflow

    // ---- GW / Q side (off-chain) ----
    float ov   = fmaxf(s_raw - 1.f, 0.f) * p.SMSC;   // max(s - SMSC, 0)
    float RECn = fmaf(RMO, g, ov);                   // REC + overflow, >= 0
    float BAS  = fmaxf(p.RecK * GW, 0.f);
    float q    = fmaf(su, RMO, INR - RMO) + BAS;     // SRUN + IRUN + BAS

    GW = GW + (RECn - BAS);
    u  = u_new;
    return q;
}

template <int T>
__global__ __launch_bounds__(32)
void hirnn_kernel(const float* __restrict__ in,
                  const float* __restrict__ pINSC,
                  const float* __restrict__ pCOEFF,
                  const float* __restrict__ pSQ,
                  const float* __restrict__ pSMSC,
                  const float* __restrict__ pSUB,
                  const float* __restrict__ pCRAK,
                  const float* __restrict__ pRecK,
                  float* __restrict__ out, int B)
{
    int bidx = blockIdx.x * 32 + threadIdx.x;
    if (bidx >= B) return;

    Params p;
    p.INSC   = fminf(fmaxf(pINSC[0]  * 5.f,   0.5f),   5.f);
    float CO = fminf(fmaxf(pCOEFF[0] * 400.f, 50.f),   400.f);
    float SQ = fminf(fmaxf(pSQ[0]    * 6.f,   0.f),    6.f);
    p.SMSC   = fminf(fmaxf(pSMSC[0]  * 500.f, 50.f),   500.f);
    p.SUB    = fminf(fmaxf(pSUB[0],           0.f),    1.f);
    p.CRAK   = fminf(fmaxf(pCRAK[0],          0.f),    1.f);
    p.RecK   = fminf(fmaxf(pRecK[0]  * 0.3f,  0.003f), 0.3f);
    p.invSMSC = 1.f / p.SMSC;
    p.ck2 = -SQ * 1.44269504088896340736f;   // -SQ * log2(e)  (arg in u-units)
    p.lC  = __log2f(CO);

    const float4* row  = reinterpret_cast<const float4*>(in + (size_t)bidx * T * 2);
    float4*       orow = reinterpret_cast<float4*>(out + (size_t)bidx * T);

    float u = 0.f, GW = 0.f;
    float Prec0 = 0.f, PET0 = 0.f;

    #pragma unroll 4
    for (int i = 0; i < T / 4; ++i) {
        float4 v0 = __ldg(&row[2 * i]);
        float4 v1 = __ldg(&row[2 * i + 1]);
        if (i == 0) { Prec0 = v0.x; PET0 = v0.y; }
        float4 q;
        q.x = stepq(v0.x, v0.y, u, GW, p);
        q.y = stepq(v0.z, v0.w, u, GW, p);
        q.z = stepq(v1.x, v1.y, u, GW, p);
        q.w = stepq(v1.z, v1.w, u, GW, p);
        orow[i] = q;   // q.x at i==0 is a placeholder, overwritten below
    }

    // Q[0]: roll(shift=1) puts the FINAL state at t=0.
    float u2 = u, G2 = GW;
    float q0 = stepq(Prec0, PET0, u2, G2, p);
    out[(size_t)bidx * T] = q0;
}

extern "C" void kernel_launch(void* const* d_in, const int* in_sizes, int n_in,
                              void* d_out, int out_size)
{
    const float* in    = (const float*)d_in[0];
    const float* INSC  = (const float*)d_in[1];
    const float* COEFF = (const float*)d_in[2];
    const float* SQ    = (const float*)d_in[3];
    const float* SMSC  = (const float*)d_in[4];
    const float* SUB   = (const float*)d_in[5];
    const float* CRAK  = (const float*)d_in[6];
    const float* RecK  = (const float*)d_in[7];
    float* out = (float*)d_out;

    constexpr int T = 1024;
    int B = out_size / T;
    int blocks = (B + 31) / 32;
    hirnn_kernel<T><<<blocks, 32>>>(in, INSC, COEFF, SQ, SMSC, SUB, CRAK, RecK,
                                    out, B);
}